// round 14
// baseline (speedup 1.0000x reference)
#include <cuda_runtime.h>
#include <cuda_fp16.h>
#include <cstdint>

// Problem constants (fixed by setup_inputs)
#define BATCH 4
#define SEQ   2048
#define EDIM  512
#define HNUM  8
#define RNUM  16
#define DDIM  64
#define TOK   (BATCH * SEQ)      // 8192 tokens
#define ERDIM (EDIM * RNUM)      // 8192 Wv rows

// K1/K4 (fp16, K=512, tile 64x128, BK=32, grid 512)
#define NCH16   16
#define G_ROWB  80               // 64B data + 16B pad
#define G_AT    (64  * G_ROWB)   // 5120
#define G_BT    (128 * G_ROWB)   // 10240
#define G_STAGE (G_AT + G_BT)    // 15360

// K3 (fp16, K=512, tile 128x128, BK=64, 128 threads, 3-stage pipeline)
#define K7_NCH   8               // 512 / 64
#define K7_RX    144             // 128B data + 16B pad
#define K7_AT    (128 * K7_RX)   // 18432 (A tile == B tile)
#define K7_STAGE (2 * K7_AT)     // 36864
#define K7_SMEM  (3 * K7_STAGE)  // 110592 (3 stages; 2 CTAs/SM = 221KB)

// Scratch (allocation-free: __device__ globals)
__device__ float g_Q[TOK * EDIM];              // scaled query projection (fp32)
__device__ float g_attn[TOK * HNUM * RNUM];    // softmax over rules
__device__ float g_iw2[HNUM * RNUM * DDIM];    // 1 / rules_widths^2
__device__ __half g_Vh[(size_t)TOK   * EDIM];  // value  fp16
__device__ __half g_Qh[(size_t)TOK   * EDIM];  // query  fp16
__device__ __half g_Wvh[(size_t)ERDIM * EDIM]; // Wv     fp16
__device__ __half g_Wqh[(size_t)EDIM * EDIM];  // Wq     fp16
__device__ __half g_Woh[(size_t)EDIM * EDIM];  // Wo     fp16
__device__ __half g_Fh[(size_t)TOK   * EDIM];  // F fp16, (b,h,s,d) row order

// ---------------------------------------------------------------------------
// Portable PTX helpers (sm_80+)
// ---------------------------------------------------------------------------
__device__ __forceinline__ uint32_t smem_u32(const void* p) {
    uint32_t a;
    asm("{ .reg .u64 t; cvta.to.shared.u64 t, %1; cvt.u32.u64 %0, t; }"
        : "=r"(a) : "l"(p));
    return a;
}
__device__ __forceinline__ void cp_async16(uint32_t dst, const void* src) {
    asm volatile("cp.async.cg.shared.global [%0], [%1], 16;"
                 :: "r"(dst), "l"(src) : "memory");
}
__device__ __forceinline__ void ldmatrix_x4(uint32_t* r, uint32_t addr) {
    asm volatile("ldmatrix.sync.aligned.m8n8.x4.shared.b16 {%0,%1,%2,%3}, [%4];"
                 : "=r"(r[0]), "=r"(r[1]), "=r"(r[2]), "=r"(r[3]) : "r"(addr));
}
__device__ __forceinline__ void mma_fp16(float* c, const uint32_t* a,
                                         uint32_t b0, uint32_t b1) {
    asm volatile(
        "mma.sync.aligned.m16n8k16.row.col.f32.f16.f16.f32 "
        "{%0,%1,%2,%3}, {%4,%5,%6,%7}, {%8,%9}, {%0,%1,%2,%3};"
        : "+f"(c[0]), "+f"(c[1]), "+f"(c[2]), "+f"(c[3])
        : "r"(a[0]), "r"(a[1]), "r"(a[2]), "r"(a[3]), "r"(b0), "r"(b1));
}

// ---------------------------------------------------------------------------
// ONE merged preprocessing kernel: 5 fp32->fp16 converts + iw2.
// ---------------------------------------------------------------------------
#define N4_TOK  (TOK * EDIM / 4)     // 1048576
#define N4_WV   (ERDIM * EDIM / 4)   // 1048576
#define N4_W    (EDIM * EDIM / 4)    // 65536
#define R0 (N4_TOK)
#define R1 (2 * N4_TOK)
#define R2 (R1 + N4_WV)
#define R3 (R2 + N4_W)
#define R4 (R3 + N4_W)               // 3276800
#define PREP_GRID ((R4 + HNUM * RNUM * DDIM) / 256)   // 12832

__device__ __forceinline__ void conv4(const float* __restrict__ s,
                                      __half* __restrict__ d, size_t i) {
    float4 v = ((const float4*)s)[i];
    *(__half2*)(d + i * 4)     = __halves2half2(__float2half_rn(v.x), __float2half_rn(v.y));
    *(__half2*)(d + i * 4 + 2) = __halves2half2(__float2half_rn(v.z), __float2half_rn(v.w));
}

__global__ __launch_bounds__(256) void prep_all_kernel(
    const float* __restrict__ value, const float* __restrict__ query,
    const float* __restrict__ Wv, const float* __restrict__ Wq,
    const float* __restrict__ Wo, const float* __restrict__ rw)
{
    size_t i = (size_t)blockIdx.x * 256 + threadIdx.x;
    if      (i < R0) conv4(value, g_Vh,  i);
    else if (i < R1) conv4(query, g_Qh,  i - R0);
    else if (i < R2) conv4(Wv,    g_Wvh, i - R1);
    else if (i < R3) conv4(Wq,    g_Wqh, i - R2);
    else if (i < R4) conv4(Wo,    g_Woh, i - R3);
    else {
        int j = (int)(i - R4);            // 8192 iw2 elements
        float t = 1.0f / rw[j];
        g_iw2[j] = t * t;
    }
}

// ---------------------------------------------------------------------------
// K2: fuzzy rule attention. One warp per (token, head); all 32 lanes active.
// ---------------------------------------------------------------------------
__global__ __launch_bounds__(256) void attn_kernel(const float* __restrict__ rk)
{
    __shared__ float qs[EDIM];
    const int token = blockIdx.x;
    {
        const float4* src = (const float4*)(g_Q + (size_t)token * EDIM);
        float4* dst = (float4*)qs;
        if (threadIdx.x < 128) dst[threadIdx.x] = src[threadIdx.x];
    }
    __syncthreads();

    const int h    = threadIdx.x >> 5;
    const int lane = threadIdx.x & 31;

    const float qa = qs[h * DDIM + lane];
    const float qb = qs[h * DDIM + lane + 32];

    float z = 0.f;
    #pragma unroll
    for (int r = 0; r < RNUM; r++) {
        const float* rp = rk    + (size_t)(h * RNUM + r) * DDIM;
        const float* wp = g_iw2 + (size_t)(h * RNUM + r) * DDIM;
        float d0 = qa - rp[lane];
        float d1 = qb - rp[lane + 32];
        float s  = d0 * d0 * wp[lane] + d1 * d1 * wp[lane + 32];
        #pragma unroll
        for (int o = 16; o; o >>= 1) s += __shfl_xor_sync(0xffffffffu, s, o);
        if (lane == r) z = s;
    }

    if (lane < 16) {
        z *= -0.5f / DDIM;
        float m = z;
        #pragma unroll
        for (int o = 8; o; o >>= 1) m = fmaxf(m, __shfl_xor_sync(0x0000ffffu, m, o));
        float e = expf(z - m);
        float sum = e;
        #pragma unroll
        for (int o = 8; o; o >>= 1) sum += __shfl_xor_sync(0x0000ffffu, sum, o);
        g_attn[(size_t)token * (HNUM * RNUM) + h * RNUM + lane] = e / sum;
    }
}

// ---------------------------------------------------------------------------
// K1/K4: plain fp16 HMMA GEMM, K=512, tile 64x128 (M x N), BK=32,
// double-buffered, 256 threads (warps 2(M) x 4(N), warp tile 32x32).
// grid = (4, 128) = 512 CTAs -> better wave balance than 128x128/256.
// K-accumulation order identical to the proven 128x128 version.
// ---------------------------------------------------------------------------
__global__ __launch_bounds__(256) void hmma_gemm16_kernel(
    const __half* __restrict__ A, const __half* __restrict__ B,
    const float* __restrict__ bias, float* __restrict__ C, float scale)
{
    __shared__ __align__(16) char smem[2 * G_STAGE];   // 30720
    const uint32_t sbase = smem_u32(smem);

    const int tid    = threadIdx.x;
    const int lane   = tid & 31;
    const int wid    = tid >> 5;
    const int warp_m = wid & 1;     // 2 x 32 rows
    const int warp_n = wid >> 1;    // 4 x 32 cols
    const int m0     = blockIdx.y * 64;
    const int n0     = blockIdx.x * 128;

    float acc[2][4][4] = {};

    auto load_chunk = [&](int c, int buf) {
        const uint32_t s0 = sbase + (uint32_t)buf * G_STAGE;
        {   // A: 64 rows x 4 x 16B = 256 slots
            const int row = tid >> 2;
            const int c16 = tid & 3;
            cp_async16(s0 + (uint32_t)row * G_ROWB + (uint32_t)c16 * 16,
                       A + (size_t)(m0 + row) * EDIM + c * 32 + c16 * 8);
        }
        #pragma unroll
        for (int t = 0; t < 2; t++) {  // B: 128 rows x 4 x 16B = 512 slots
            const int idx = tid + t * 256;
            const int row = idx >> 2;
            const int c16 = idx & 3;
            cp_async16(s0 + G_AT + (uint32_t)row * G_ROWB + (uint32_t)c16 * 16,
                       B + (size_t)(n0 + row) * EDIM + c * 32 + c16 * 8);
        }
        asm volatile("cp.async.commit_group;" ::: "memory");
    };

    const uint32_t lm_row = (uint32_t)(lane & 15);
    const uint32_t lm_kb  = (uint32_t)(lane >> 4) * 16;

    load_chunk(0, 0);

    for (int c = 0; c < NCH16; c++) {
        const int buf = c & 1;
        if (c + 1 < NCH16) {
            load_chunk(c + 1, buf ^ 1);
            asm volatile("cp.async.wait_group 1;" ::: "memory");
        } else {
            asm volatile("cp.async.wait_group 0;" ::: "memory");
        }
        __syncthreads();

        const uint32_t a_s = sbase + (uint32_t)buf * G_STAGE;
        const uint32_t b_s = a_s + G_AT;

        #pragma unroll
        for (int ks = 0; ks < 2; ks++) {
            const uint32_t kb = (uint32_t)ks * 32 + lm_kb;
            uint32_t afr[2][4];
            #pragma unroll
            for (int mt = 0; mt < 2; mt++) {
                const uint32_t row = (uint32_t)(warp_m * 32 + mt * 16) + lm_row;
                ldmatrix_x4(afr[mt], a_s + row * G_ROWB + kb);
            }
            uint32_t bfr[2][4];
            #pragma unroll
            for (int np = 0; np < 2; np++) {
                const uint32_t row = (uint32_t)(warp_n * 32 + np * 16) + lm_row;
                ldmatrix_x4(bfr[np], b_s + row * G_ROWB + kb);
            }
            #pragma unroll
            for (int mt = 0; mt < 2; mt++)
                #pragma unroll
                for (int nt = 0; nt < 4; nt++)
                    mma_fp16(acc[mt][nt], afr[mt],
                             bfr[nt >> 1][nt & 1], bfr[nt >> 1][(nt & 1) + 2]);
        }
        __syncthreads();
    }

    const int q  = lane & 3;
    const int rg = lane >> 2;
    #pragma unroll
    for (int mt = 0; mt < 2; mt++) {
        #pragma unroll
        for (int half = 0; half < 2; half++) {
            const int row = m0 + warp_m * 32 + mt * 16 + rg + half * 8;
            #pragma unroll
            for (int nt = 0; nt < 4; nt++) {
                const int col = n0 + warp_n * 32 + nt * 8 + q * 2;
                float2 v;
                v.x = (acc[mt][nt][half * 2 + 0] + bias[col])     * scale;
                v.y = (acc[mt][nt][half * 2 + 1] + bias[col + 1]) * scale;
                *(float2*)(C + (size_t)row * EDIM + col) = v;
            }
        }
    }
}

// ---------------------------------------------------------------------------
// K3 v7: fp16 single-product GEMM + fused fuzzy epilogue.
// Tile 128x128, 128 threads (warps 2(M) x 2(N), warp tile 64x64), BK=64,
// THREE-stage cp.async pipeline: steady-state wait_group 1 keeps one load
// group always in flight (no per-chunk drain). 2 CTAs/SM (221KB smem).
// Writes g_Fh fp16 in (b,h,s,d) row order.
// ---------------------------------------------------------------------------
__global__ void __launch_bounds__(128, 2) hmma_fused_v7_kernel(const float* __restrict__ bv)
{
    extern __shared__ __align__(16) char smem[];
    const uint32_t sbase = smem_u32(smem);

    const int tid    = threadIdx.x;
    const int lane   = tid & 31;
    const int wid    = tid >> 5;
    const int warp_m = wid & 1;     // 2 x 64 rows
    const int warp_n = wid >> 1;    // 2 x 64 cols
    const int m0     = blockIdx.y * 128;   // token base
    const int n0     = blockIdx.x * 128;   // Wv-row base

    float acc[4][8][4] = {};   // [mt 16-row][nt 8-col][frag]

    auto load_chunk = [&](int c, int buf) {
        const uint32_t s0 = sbase + (uint32_t)buf * K7_STAGE;
        #pragma unroll
        for (int i = 0; i < 8; i++) {        // A: 128 rows x 8 x 16B
            const int idx = tid + i * 128;
            const int row = idx >> 3;
            const int c16 = idx & 7;
            cp_async16(s0 + (uint32_t)row * K7_RX + (uint32_t)c16 * 16,
                       g_Vh + (size_t)(m0 + row) * EDIM + c * 64 + c16 * 8);
        }
        #pragma unroll
        for (int i = 0; i < 8; i++) {        // B: 128 rows x 8 x 16B
            const int idx = tid + i * 128;
            const int row = idx >> 3;
            const int c16 = idx & 7;
            cp_async16(s0 + K7_AT + (uint32_t)row * K7_RX + (uint32_t)c16 * 16,
                       g_Wvh + (size_t)(n0 + row) * EDIM + c * 64 + c16 * 8);
        }
        asm volatile("cp.async.commit_group;" ::: "memory");
    };

    const uint32_t lm_row = (uint32_t)(lane & 15);
    const uint32_t lm_kb  = (uint32_t)(lane >> 4) * 16;

    // prologue: two stages in flight
    load_chunk(0, 0);
    load_chunk(1, 1);

    for (int c = 0; c < K7_NCH; c++) {
        if (c + 1 < K7_NCH) {
            asm volatile("cp.async.wait_group 1;" ::: "memory");  // stage c ready
        } else {
            asm volatile("cp.async.wait_group 0;" ::: "memory");
        }
        __syncthreads();
        // buffer (c+2)%3 was last read in chunk c-1; all warps passed the
        // sync above after finishing it -> safe to overwrite.
        if (c + 2 < K7_NCH) load_chunk(c + 2, (c + 2) % 3);

        const uint32_t a_s = sbase + (uint32_t)(c % 3) * K7_STAGE;
        const uint32_t b_s = a_s + K7_AT;

        #pragma unroll
        for (int ks = 0; ks < 4; ks++) {     // four K=16 steps per 64-chunk
            const uint32_t kb = (uint32_t)ks * 32 + lm_kb;
            uint32_t afr[4][4];
            uint32_t bfr[4][4];
            #pragma unroll
            for (int nb = 0; nb < 4; nb++) {
                const uint32_t row = (uint32_t)(warp_n * 64 + nb * 16) + lm_row;
                ldmatrix_x4(bfr[nb], b_s + row * K7_RX + kb);
            }
            #pragma unroll
            for (int mt = 0; mt < 4; mt++) {
                const uint32_t row = (uint32_t)(warp_m * 64 + mt * 16) + lm_row;
                ldmatrix_x4(afr[mt], a_s + row * K7_RX + kb);
            }
            #pragma unroll
            for (int mt = 0; mt < 4; mt++)
                #pragma unroll
                for (int nt = 0; nt < 8; nt++)
                    mma_fp16(acc[mt][nt], afr[mt],
                             bfr[nt >> 1][nt & 1], bfr[nt >> 1][(nt & 1) + 2]);
        }
    }

    // -------- fused fuzzy epilogue (writes fp16 F) --------
    const int q   = lane & 3;
    const int rg  = lane >> 2;
    const int hd0 = n0 >> 4;
    const int h   = hd0 >> 6;
    const int d0c = hd0 & 63;

    float bvv[4][4];   // [g][ntl*2+j]
    #pragma unroll
    for (int g = 0; g < 4; g++)
        #pragma unroll
        for (int ntl = 0; ntl < 2; ntl++)
            #pragma unroll
            for (int j = 0; j < 2; j++)
                bvv[g][ntl * 2 + j] =
                    __ldg(bv + n0 + warp_n * 64 + g * 16 + ntl * 8 + q * 2 + j);

    #pragma unroll
    for (int mt = 0; mt < 4; mt++) {
        #pragma unroll
        for (int half = 0; half < 2; half++) {
            const int rowm  = warp_m * 64 + mt * 16 + rg + half * 8;
            const int token = m0 + rowm;
            const int b     = token >> 11;
            const int s     = token & 2047;
            const float* ap = g_attn + (size_t)token * (HNUM * RNUM) + h * RNUM;
            const float at0 = ap[q * 2],     at1 = ap[q * 2 + 1];
            const float at2 = ap[q * 2 + 8], at3 = ap[q * 2 + 9];

            // (b,h,s,d) flattened to [8192 x 512]
            const int frow  = (b * HNUM + h) * 256 + (s >> 3);
            const int cbase = (s & 7) * 64;

            #pragma unroll
            for (int g = 0; g < 4; g++) {
                float p = (acc[mt][g * 2 + 0][half * 2 + 0] + bvv[g][0]) * at0
                        + (acc[mt][g * 2 + 0][half * 2 + 1] + bvv[g][1]) * at1
                        + (acc[mt][g * 2 + 1][half * 2 + 0] + bvv[g][2]) * at2
                        + (acc[mt][g * 2 + 1][half * 2 + 1] + bvv[g][3]) * at3;
                p += __shfl_down_sync(0xffffffffu, p, 2);
                p += __shfl_down_sync(0xffffffffu, p, 1);
                if (q == 0) {
                    p *= 0.125f;  // D^-0.5
                    const int col = cbase + d0c + warp_n * 4 + g;
                    g_Fh[(size_t)frow * EDIM + col] = __float2half_rn(p);
                }
            }
        }
    }
}

// ---------------------------------------------------------------------------
extern "C" void kernel_launch(void* const* d_in, const int* in_sizes, int n_in,
                              void* d_out, int out_size)
{
    const float* query = (const float*)d_in[0];
    // d_in[1] = key: unused by the reference computation
    const float* value = (const float*)d_in[2];
    const float* Wq    = (const float*)d_in[3];
    const float* bq    = (const float*)d_in[4];
    const float* Wv    = (const float*)d_in[5];
    const float* bv    = (const float*)d_in[6];
    const float* Wo    = (const float*)d_in[7];
    const float* bo    = (const float*)d_in[8];
    const float* rk    = (const float*)d_in[9];
    const float* rw    = (const float*)d_in[10];
    float* out = (float*)d_out;

    float* Qp = nullptr;
    __half *Qh = nullptr, *Wqh = nullptr, *Woh = nullptr, *Fh = nullptr;
    cudaGetSymbolAddress((void**)&Qp,  g_Q);
    cudaGetSymbolAddress((void**)&Qh,  g_Qh);
    cudaGetSymbolAddress((void**)&Wqh, g_Wqh);
    cudaGetSymbolAddress((void**)&Woh, g_Woh);
    cudaGetSymbolAddress((void**)&Fh,  g_Fh);

    cudaFuncSetAttribute(hmma_fused_v7_kernel,
                         cudaFuncAttributeMaxDynamicSharedMemorySize, K7_SMEM);

    dim3 blk(256);

    // 1: ALL preprocessing in one launch (5 converts + iw2)
    prep_all_kernel<<<dim3(PREP_GRID), blk>>>(value, query, Wv, Wq, Wo, rw);

    // 2: K1 q projection (scaled), grid 512
    hmma_gemm16_kernel<<<dim3(EDIM / 128, TOK / 64), blk>>>(
        Qh, Wqh, bq, Qp, 0.125f);

    // 3: K2 fuzzy rule attention
    attn_kernel<<<dim3(TOK), blk>>>(rk);

    // 4: K3 fused v-GEMM + rule reduction (3-stage pipeline)
    hmma_fused_v7_kernel<<<dim3(ERDIM / 128, TOK / 128), dim3(128), K7_SMEM>>>(bv);

    // 5: K4 output projection (reads g_Fh directly), grid 512
    hmma_gemm16_kernel<<<dim3(EDIM / 128, TOK / 64), blk>>>(
        Fh, Woh, bo, out, 1.0f);
}